// round 16
// baseline (speedup 1.0000x reference)
#include <cuda_runtime.h>
#include <cuda_fp16.h>

#define N_NODES 50000
#define N_FEAT  128
#define N_EDGES 600000
#define N_POWERS 3

// fp16 staging copy of x (halves gather traffic + L1 wavefronts).
__device__ __half g_x16[(size_t)N_NODES * N_FEAT];

// 1 if edge_index is genuinely int64 on device, 0 if int32 (JAX x64-off).
__device__ int g_idx_is64;

__global__ void __launch_bounds__(256)
convert_x_kernel(const float* __restrict__ x, const int* __restrict__ ei32)
{
    if (blockIdx.x == 0 && threadIdx.x == 0) {
        int all_zero = 1;
#pragma unroll
        for (int k = 1; k < 256; k += 2) all_zero &= (ei32[k] == 0);
        g_idx_is64 = all_zero;
    }
    const int i = (blockIdx.x * blockDim.x + threadIdx.x) * 4;
    if (i < N_NODES * N_FEAT) {
        const float4 v = *reinterpret_cast<const float4*>(x + i);
        __half2 h0 = __floats2half2_rn(v.x, v.y);
        __half2 h1 = __floats2half2_rn(v.z, v.w);
        uint2 packed;
        packed.x = *reinterpret_cast<unsigned*>(&h0);
        packed.y = *reinterpret_cast<unsigned*>(&h1);
        *reinterpret_cast<uint2*>(&g_x16[i]) = packed;
    }
}

// abs via sign-mask (LOP3 on alu pipe instead of HABS2 on fma pipe).
static __device__ __forceinline__ __half2 habs2_and(__half2 v) {
    unsigned u = *reinterpret_cast<unsigned*>(&v) & 0x7FFF7FFFu;
    return *reinterpret_cast<__half2*>(&u);
}

// Fold half2 -> float (sum of both halves).
static __device__ __forceinline__ float hfold(__half2 a) {
    return __low2float(__hadd2(a, __lowhigh2highlow(a)));
}

// Fold two half2 accumulators into one packed half2 (lane-local sums).
static __device__ __forceinline__ __half2 hfold_pack(__half2 a, __half2 b) {
    const __half2 sa = __hadd2(a, __lowhigh2highlow(a));
    const __half2 sb = __hadd2(b, __lowhigh2highlow(b));
    return __halves2half2(__low2half(sa), __low2half(sb));
}

static __device__ __forceinline__ __half2 shfl_xor_h2(__half2 v, int off) {
    unsigned u = *reinterpret_cast<unsigned*>(&v);
    u = __shfl_xor_sync(0xFFFFFFFFu, u, off);
    return *reinterpret_cast<__half2*>(&u);
}

// Broadcast load of 4 floats from smem (all lanes same address -> 1 wavefront).
static __device__ __forceinline__ float4 lds_f4(unsigned addr) {
    float4 v;
    asm volatile("ld.shared.v4.f32 {%0,%1,%2,%3}, [%4];"
                 : "=f"(v.x), "=f"(v.y), "=f"(v.z), "=f"(v.w) : "r"(addr));
    return v;
}

// 8 lanes per edge, 8 edges per warp-iteration (group g handles edges
// 2g, 2g+1 = streams A, B). Lane l owns features [8l,8l+8) (chunk 0) and
// [64+8l,+8) (chunk 1); each warp LDG.128 covers exactly one 128B line per
// edge-row. SINGLE-PHASE: all 8 gathers issue at iteration top (MLP=8),
// weights in registers (24). Epilogue scalars in smem (-7 regs). 128-thread
// blocks with __launch_bounds__(128,7): reg cap 73 -> 7 CTAs/SM = 28 warps.
__global__ void __launch_bounds__(128, 7)
adj_learn_kernel(const void* __restrict__ edge_index_raw,
                 const float* __restrict__ Wa,
                 const float* __restrict__ ba,
                 const float* __restrict__ Wb,
                 const float* __restrict__ bb,
                 float* __restrict__ out)
{
    __shared__ __align__(16) float ec[8];   // ba0,ba1,ba2,wb0 | wb1,wb2,bbv,0

    const int p    = blockIdx.y;
    const int tid  = threadIdx.x;
    const int lane = tid & 31;
    const int l    = lane & 7;        // lane within edge-group
    const int g    = lane >> 3;       // edge-pair slot 0..3
    const int warp = tid >> 5;
    const int warps_per_block = blockDim.x >> 5;
    const int gwarp  = blockIdx.x * warps_per_block + warp;
    const int nwarps = gridDim.x * warps_per_block;

    if (tid == 0) {
        ec[0] = ba[p * 3 + 0];
        ec[1] = ba[p * 3 + 1];
        ec[2] = ba[p * 3 + 2];
        ec[3] = Wb[p * 3 + 0];
        ec[4] = Wb[p * 3 + 1];
        ec[5] = Wb[p * 3 + 2];
        ec[6] = bb[p];
        ec[7] = 0.f;
    }

    const int fA = l * 8;
    const int fB = 64 + l * 8;

    // Per-lane weights: half2 feature-pairs, k=0..3 -> chunk fA, k=4..7 -> fB.
    const float* Wap = Wa + (size_t)p * (N_FEAT * 3);
    __half2 w2[3][8];
#pragma unroll
    for (int k = 0; k < 4; ++k) {
#pragma unroll
        for (int h = 0; h < 3; ++h) {
            w2[h][k]     = __floats2half2_rn(Wap[(fA + 2 * k) * 3 + h],
                                             Wap[(fA + 2 * k + 1) * 3 + h]);
            w2[h][k + 4] = __floats2half2_rn(Wap[(fB + 2 * k) * 3 + h],
                                             Wap[(fB + 2 * k + 1) * 3 + h]);
        }
    }
    __syncthreads();

    const unsigned ec_addr = (unsigned)__cvta_generic_to_shared(ec);
    const int shift = g_idx_is64;     // 0: int32 words, 1: int64 (read low word)

    const int* ei32 = (const int*)edge_index_raw;
    const int  src_base = p * 2 * N_EDGES;        // element index
    const int  dst_base = src_base + N_EDGES;
    float* outp = out + (size_t)p * N_EDGES;

    const int n_sup = N_EDGES / 8;    // 75000 super-groups of 8 edges

    for (int si = gwarp; si < n_sup; si += nwarps) {
        const int e = si * 8 + 2 * g;
        const int sA = ei32[(size_t)(src_base + e)     << shift];
        const int sB = ei32[(size_t)(src_base + e + 1) << shift];
        const int dA = ei32[(size_t)(dst_base + e)     << shift];
        const int dB = ei32[(size_t)(dst_base + e + 1) << shift];

        const __half* rjA = &g_x16[(size_t)sA * N_FEAT];
        const __half* riA = &g_x16[(size_t)dA * N_FEAT];
        const __half* rjB = &g_x16[(size_t)sB * N_FEAT];
        const __half* riB = &g_x16[(size_t)dB * N_FEAT];

        // All 8 gathers up front (MLP = 8).
        __half2 jA0[4], jA1[4], iA0[4], iA1[4], jB0[4], jB1[4], iB0[4], iB1[4];
        *reinterpret_cast<uint4*>(jA0) = *reinterpret_cast<const uint4*>(rjA + fA);
        *reinterpret_cast<uint4*>(jA1) = *reinterpret_cast<const uint4*>(rjA + fB);
        *reinterpret_cast<uint4*>(iA0) = *reinterpret_cast<const uint4*>(riA + fA);
        *reinterpret_cast<uint4*>(iA1) = *reinterpret_cast<const uint4*>(riA + fB);
        *reinterpret_cast<uint4*>(jB0) = *reinterpret_cast<const uint4*>(rjB + fA);
        *reinterpret_cast<uint4*>(jB1) = *reinterpret_cast<const uint4*>(rjB + fB);
        *reinterpret_cast<uint4*>(iB0) = *reinterpret_cast<const uint4*>(riB + fA);
        *reinterpret_cast<uint4*>(iB1) = *reinterpret_cast<const uint4*>(riB + fB);

        __half2 a0A = __float2half2_rn(0.f), a1A = a0A, a2A = a0A;
        __half2 a0B = a0A, a1B = a0A, a2B = a0A;

#pragma unroll
        for (int k = 0; k < 4; ++k) {
            const __half2 dhA = habs2_and(__hsub2(jA0[k], iA0[k]));
            const __half2 dhB = habs2_and(__hsub2(jB0[k], iB0[k]));
            a0A = __hfma2(dhA, w2[0][k], a0A);
            a0B = __hfma2(dhB, w2[0][k], a0B);
            a1A = __hfma2(dhA, w2[1][k], a1A);
            a1B = __hfma2(dhB, w2[1][k], a1B);
            a2A = __hfma2(dhA, w2[2][k], a2A);
            a2B = __hfma2(dhB, w2[2][k], a2B);
        }
#pragma unroll
        for (int k = 0; k < 4; ++k) {
            const __half2 dhA = habs2_and(__hsub2(jA1[k], iA1[k]));
            const __half2 dhB = habs2_and(__hsub2(jB1[k], iB1[k]));
            a0A = __hfma2(dhA, w2[0][k + 4], a0A);
            a0B = __hfma2(dhB, w2[0][k + 4], a0B);
            a1A = __hfma2(dhA, w2[1][k + 4], a1A);
            a1B = __hfma2(dhB, w2[1][k + 4], a1B);
            a2A = __hfma2(dhA, w2[2][k + 4], a2A);
            a2B = __hfma2(dhB, w2[2][k + 4], a2B);
        }

        // Fold: (h0,h1) packed as half2, h2 as fp32, per stream.
        const __half2 pkA = hfold_pack(a0A, a1A);
        const __half2 pkB = hfold_pack(a0B, a1B);
        const float   x2A = hfold(a2A);
        const float   x2B = hfold(a2B);

        // Parity-interleaved butterfly over the 8-lane group.
        const bool oddl = (lane & 1);
        __half2 pk_keep = oddl ? pkB : pkA;
        __half2 pk_send = oddl ? pkA : pkB;
        float   x2_keep = oddl ? x2B : x2A;
        float   x2_send = oddl ? x2A : x2B;

        __half2 pk = __hadd2(pk_keep, shfl_xor_h2(pk_send, 1));
        float   x2 = x2_keep + __shfl_xor_sync(0xFFFFFFFFu, x2_send, 1);
#pragma unroll
        for (int off = 2; off <= 4; off <<= 1) {
            pk = __hadd2(pk, shfl_xor_h2(pk, off));
            x2 += __shfl_xor_sync(0xFFFFFFFFu, x2, off);
        }
        // Lane 8g holds edge 2g's (h0,h1,h2); lane 8g+1 holds edge 2g+1's.

        // Epilogue constants from smem (broadcast, 2 wavefronts).
        const float4 c0 = lds_f4(ec_addr);        // ba0,ba1,ba2,wb0
        const float4 c1 = lds_f4(ec_addr + 16);   // wb1,wb2,bbv,0

        const float y0 = __low2float(pk);
        const float y1 = __high2float(pk);
        const float h0 = fmaxf(y0 + c0.x, 0.f);
        const float h1 = fmaxf(y1 + c0.y, 0.f);
        const float h2 = fmaxf(x2 + c0.z, 0.f);
        const float z  = h0 * c0.w + h1 * c1.x + h2 * c1.y + c1.z;
        const float r  = __fdividef(1.0f, 1.0f + __expf(-z));
        // Lanes {8g, 8g+1} store edges {2g, 2g+1}: one 32B coalesced store.
        if (l < 2) outp[si * 8 + 2 * g + (lane & 1)] = r;
    }
}

extern "C" void kernel_launch(void* const* d_in, const int* in_sizes, int n_in,
                              void* d_out, int out_size)
{
    const float* x  = (const float*)d_in[0];
    const void*  ei = d_in[1];
    const float* Wa = (const float*)d_in[2];
    const float* ba = (const float*)d_in[3];
    const float* Wb = (const float*)d_in[4];
    const float* bb = (const float*)d_in[5];
    float* out = (float*)d_out;

    convert_x_kernel<<<(N_NODES * N_FEAT / 4 + 255) / 256, 256>>>(x, (const int*)ei);

    // 1035 CTAs ~= one wave at 7 CTAs/SM x 148 SMs.
    dim3 grid(345, N_POWERS, 1);
    dim3 block(128, 1, 1);
    adj_learn_kernel<<<grid, block>>>(ei, Wa, ba, Wb, bb, out);
}